// round 2
// baseline (speedup 1.0000x reference)
#include <cuda_runtime.h>
#include <math.h>
#include <stdint.h>

// Problem constants
#define BB   128
#define NN   256
#define DIN  128
#define HH   8
#define DK   16
#define HK   128            // H*DK
#define ROWS (BB*NN)        // 32768
#define NORMC 0.25f         // 1/sqrt(16)

// ---------------- device-global scratch (no allocations allowed) ----------------
__device__ float g_Q[(size_t)ROWS * HK];      // [b*N+n][h*16+k]
__device__ float g_K[(size_t)ROWS * HK];
__device__ float g_V[(size_t)ROWS * HK];
__device__ float g_heads[(size_t)ROWS * HK];  // [b*N+q][h*16+v]
__device__ float g_attn[(size_t)HH * BB * NN * NN]; // [h][b][i][j]  (268 MB)

// =====================================================================
// Generic 128-wide GEMM: Out[row][c] = sum_d A[row][d] * W[d][c]
// mode 0: W comes from per-head layout (H, DIN, 16): W[d][c]=raw[(c/16)*DIN*16 + d*16 + c%16]
// mode 1: W row-major (128,128)
// grid: ROWS/64 blocks, 256 threads. dyn smem = (128*128 + 64*129)*4
// =====================================================================
__global__ void gemm128_kernel(const float* __restrict__ A,
                               const float* __restrict__ Wraw,
                               float* __restrict__ Out,
                               int mode)
{
    extern __shared__ float sm[];
    float* Wsm = sm;              // [128][128]
    float* Asm = sm + 128 * 128;  // [64][129]

    const int tid = threadIdx.x;
    const int row0 = blockIdx.x * 64;

    for (int idx = tid; idx < 128 * 128; idx += 256) {
        int d = idx >> 7, c = idx & 127;
        float w;
        if (mode == 0) w = Wraw[(c >> 4) * (DIN * 16) + d * 16 + (c & 15)];
        else           w = Wraw[d * 128 + c];
        Wsm[d * 128 + c] = w;
    }
    for (int idx = tid; idx < 64 * 128; idx += 256) {
        int r = idx >> 7, d = idx & 127;
        Asm[r * 129 + d] = A[(size_t)(row0 + r) * 128 + d];
    }
    __syncthreads();

    const int tx = tid & 15, ty = tid >> 4;
    const int c0 = tx * 8;
    const int r0 = ty * 4;
    float acc[4][8];
#pragma unroll
    for (int u = 0; u < 4; u++)
#pragma unroll
        for (int k = 0; k < 8; k++) acc[u][k] = 0.f;

#pragma unroll 4
    for (int d = 0; d < 128; d++) {
        float wv[8];
#pragma unroll
        for (int k = 0; k < 8; k++) wv[k] = Wsm[d * 128 + c0 + k];
#pragma unroll
        for (int u = 0; u < 4; u++) {
            float a = Asm[(r0 + u) * 129 + d];
#pragma unroll
            for (int k = 0; k < 8; k++) acc[u][k] = fmaf(a, wv[k], acc[u][k]);
        }
    }
#pragma unroll
    for (int u = 0; u < 4; u++)
#pragma unroll
        for (int k = 0; k < 8; k++)
            Out[(size_t)(row0 + r0 + u) * 128 + c0 + k] = acc[u][k];
}

// =====================================================================
// Scores kernel: per (b, 32-row i-tile). Stages K[b] (all heads) in smem,
// computes edge-MLP bias ONCE per (i,j) shared by all 8 heads, folds the
// mask into the bias (-inf), fuses QK^T*NORM + bias + softmax, writes
// probs to g_attn[h][b][i][j].
// grid (N/32=8, B=128), 512 threads.
// =====================================================================
__global__ void scores_kernel(const float* __restrict__ Ebm,
                              const int* __restrict__ mask,
                              const float* __restrict__ mw1, const float* __restrict__ mb1,
                              const float* __restrict__ mw2, const float* __restrict__ mb2,
                              const float* __restrict__ mw3, const float* __restrict__ mb3)
{
    extern __shared__ float sm[];
    float* Ksm   = sm;                       // [256][129]
    float* biasm = Ksm + 256 * 129;          // [4][256][9]
    float* Qsm   = biasm + 4 * 256 * 9;      // [4][128]
    float* w1 = Qsm + 4 * 128;               // 16
    float* b1 = w1 + 16;                     // 16
    float* w2 = b1 + 16;                     // 256
    float* b2 = w2 + 256;                    // 16
    float* w3 = b2 + 16;                     // 128
    float* b3 = w3 + 128;                    // 8

    const int tid   = threadIdx.x;           // 512
    const int b     = blockIdx.y;
    const int itile = blockIdx.x * 32;

    // stage K (all heads of this batch), padded stride 129 -> conflict-free reads
    const float* Kg = g_K + (size_t)b * NN * HK;
    for (int idx = tid; idx < NN * HK; idx += 512) {
        int j = idx >> 7, c = idx & 127;
        Ksm[j * 129 + c] = Kg[idx];
    }
    // stage MLP weights
    if (tid < 16)        w1[tid]       = mw1[tid];
    else if (tid < 32)   b1[tid - 16]  = mb1[tid - 16];
    else if (tid < 288)  w2[tid - 32]  = mw2[tid - 32];
    else if (tid < 304)  b2[tid - 288] = mb2[tid - 288];
    else if (tid < 432)  w3[tid - 304] = mw3[tid - 304];
    else if (tid < 440)  b3[tid - 432] = mb3[tid - 432];
    __syncthreads();

    const int warp = tid >> 5, lane = tid & 31;
    const int h     = warp & 7;
    const int rbase = (warp >> 3) * 2;   // rows {0,1} or {2,3} of the 4-row group

    for (int it = 0; it < 8; it++) {
        const int i0 = itile + it * 4;

        // stage 4 Q rows (512 elements, one per thread)
        {
            int r = tid >> 7, c = tid & 127;
            Qsm[r * 128 + c] = g_Q[(size_t)(b * NN + i0 + r) * HK + c];
        }

        // ---- edge MLP bias (+mask fold): 4 rows x 256 j; 2 per thread
        {
            const int j  = tid & 255;
            const int r0 = tid >> 8;      // 0/1
            const int r1 = r0 + 2;        // 2/3
            const size_t base0 = (size_t)(b * NN + i0 + r0) * NN + j;
            const size_t base1 = (size_t)(b * NN + i0 + r1) * NN + j;
            float e0 = Ebm[base0];
            float e1 = Ebm[base1];
            const int m0 = mask[base0];
            const int m1 = mask[base1];

            float h1a[16], h1b[16];
#pragma unroll
            for (int n = 0; n < 16; n++) {
                h1a[n] = fmaxf(fmaf(e0, w1[n], b1[n]), 0.f);
                h1b[n] = fmaxf(fmaf(e1, w1[n], b1[n]), 0.f);
            }
            float h2a[16], h2b[16];
#pragma unroll
            for (int c = 0; c < 16; c++) {
                float aa = b2[c], ab = b2[c];
#pragma unroll
                for (int n = 0; n < 16; n++) {
                    float wv = w2[n * 16 + c];
                    aa = fmaf(h1a[n], wv, aa);
                    ab = fmaf(h1b[n], wv, ab);
                }
                h2a[c] = fmaxf(aa, 0.f);
                h2b[c] = fmaxf(ab, 0.f);
            }
#pragma unroll
            for (int hh = 0; hh < 8; hh++) {
                float oa = b3[hh], ob = b3[hh];
#pragma unroll
                for (int c = 0; c < 16; c++) {
                    float wv = w3[c * 8 + hh];
                    oa = fmaf(h2a[c], wv, oa);
                    ob = fmaf(h2b[c], wv, ob);
                }
                biasm[(r0 * 256 + j) * 9 + hh] = m0 ? -INFINITY : oa;
                biasm[(r1 * 256 + j) * 9 + hh] = m1 ? -INFINITY : ob;
            }
        }
        __syncthreads();

        // ---- scores + softmax: warp handles (head h, rows rbase & rbase+1)
        {
            float Qa[16], Qb[16];
#pragma unroll
            for (int k = 0; k < 16; k++) {
                Qa[k] = Qsm[rbase * 128 + h * 16 + k];
                Qb[k] = Qsm[(rbase + 1) * 128 + h * 16 + k];
            }

            float sa[8], sb[8];
#pragma unroll
            for (int t = 0; t < 8; t++) {
                int j = lane + 32 * t;
                const float* kp = Ksm + j * 129 + h * 16;
                float da = 0.f, db = 0.f;
#pragma unroll
                for (int k = 0; k < 16; k++) {
                    float kv = kp[k];
                    da = fmaf(Qa[k], kv, da);
                    db = fmaf(Qb[k], kv, db);
                }
                float ba = biasm[(rbase * 256 + j) * 9 + h];
                float bb = biasm[((rbase + 1) * 256 + j) * 9 + h];
                // bias = -inf for masked entries; NORMC*d is finite so sum stays -inf
                sa[t] = (ba == -INFINITY) ? -INFINITY : fmaf(NORMC, da, ba);
                sb[t] = (bb == -INFINITY) ? -INFINITY : fmaf(NORMC, db, bb);
            }
            float ma = sa[0], mb_ = sb[0];
#pragma unroll
            for (int t = 1; t < 8; t++) { ma = fmaxf(ma, sa[t]); mb_ = fmaxf(mb_, sb[t]); }
#pragma unroll
            for (int o = 16; o > 0; o >>= 1) {
                ma  = fmaxf(ma,  __shfl_xor_sync(0xffffffffu, ma,  o));
                mb_ = fmaxf(mb_, __shfl_xor_sync(0xffffffffu, mb_, o));
            }
            float pa[8], pb[8];
            float suma = 0.f, sumb = 0.f;
#pragma unroll
            for (int t = 0; t < 8; t++) {
                pa[t] = __expf(sa[t] - ma);  suma += pa[t];
                pb[t] = __expf(sb[t] - mb_); sumb += pb[t];
            }
#pragma unroll
            for (int o = 16; o > 0; o >>= 1) {
                suma += __shfl_xor_sync(0xffffffffu, suma, o);
                sumb += __shfl_xor_sync(0xffffffffu, sumb, o);
            }
            float inva = 1.f / suma, invb = 1.f / sumb;
            float* outa = g_attn + ((((size_t)h * BB + b) * NN) + (i0 + rbase)) * NN;
            float* outb = outa + NN;
#pragma unroll
            for (int t = 0; t < 8; t++) {
                int j = lane + 32 * t;
                outa[j] = pa[t] * inva;
                outb[j] = pb[t] * invb;
            }
        }
        __syncthreads();
    }
}

// =====================================================================
// AV kernel: heads[b,q,h*16+v] = sum_j attn[h,b,q,j] * V[b,j,h*16+v]
// grid (N/32=8, B=128), 512 threads. Warp handles (h, q-pair), smem-transpose reduce.
// =====================================================================
__global__ void av_kernel()
{
    extern __shared__ float sm[];
    float* Vsm = sm;                 // [256][129]
    float* red = Vsm + 256 * 129;    // [16 warps][32 lanes][34]

    const int tid = threadIdx.x;     // 512
    const int b   = blockIdx.y;
    const int qt  = blockIdx.x * 32;

    const float* Vg = g_V + (size_t)b * NN * HK;
    for (int idx = tid; idx < NN * HK; idx += 512) {
        int j = idx >> 7, c = idx & 127;
        Vsm[j * 129 + c] = Vg[idx];
    }
    __syncthreads();

    const int warp = tid >> 5, lane = tid & 31;
    float* myred = red + warp * 32 * 34;

    for (int task = warp; task < 128; task += 16) {
        const int h  = task & 7;
        const int qp = task >> 3;
        const int qa = qt + qp * 2;
        const float* pa = g_attn + ((((size_t)h * BB + b) * NN) + qa) * NN;
        const float* pb = pa + NN;

        float va[16], vb[16];
#pragma unroll
        for (int v = 0; v < 16; v++) { va[v] = 0.f; vb[v] = 0.f; }

#pragma unroll
        for (int t = 0; t < 8; t++) {
            int j = lane + 32 * t;
            float aa = pa[j], ab = pb[j];
            const float* vp = Vsm + j * 129 + h * 16;
#pragma unroll
            for (int v = 0; v < 16; v++) {
                float vv = vp[v];
                va[v] = fmaf(aa, vv, va[v]);
                vb[v] = fmaf(ab, vv, vb[v]);
            }
        }
#pragma unroll
        for (int v = 0; v < 16; v++) {
            myred[lane * 34 + v]      = va[v];
            myred[lane * 34 + 17 + v] = vb[v];
        }
        __syncwarp();
        // lane l: q-select = l>>4, v = l&15 ; sum over 32 partial rows
        float s = 0.f;
        const int off = (lane >> 4) * 17 + (lane & 15);
#pragma unroll
        for (int r = 0; r < 32; r++) s += myred[r * 34 + off];
        const int q = qa + (lane >> 4);
        g_heads[(size_t)(b * NN + q) * HK + h * 16 + (lane & 15)] = s;
        __syncwarp();
    }
}

// =====================================================================
// host launcher
// =====================================================================
extern "C" void kernel_launch(void* const* d_in, const int* in_sizes, int n_in,
                              void* d_out, int out_size)
{
    (void)in_sizes; (void)n_in; (void)out_size;
    const float* q    = (const float*)d_in[0];
    const float* hx   = (const float*)d_in[1];
    const int*   mask = (const int*)d_in[2];     // bool serialized as int32
    const float* edge = (const float*)d_in[3];
    const float* Wq   = (const float*)d_in[4];
    const float* Wk   = (const float*)d_in[5];
    const float* Wv   = (const float*)d_in[6];
    const float* Wo   = (const float*)d_in[7];
    const float* mw1  = (const float*)d_in[8];
    const float* mb1  = (const float*)d_in[9];
    const float* mw2  = (const float*)d_in[10];
    const float* mb2  = (const float*)d_in[11];
    const float* mw3  = (const float*)d_in[12];
    const float* mb3  = (const float*)d_in[13];

    float *gQ, *gK, *gV, *gH;
    cudaGetSymbolAddress((void**)&gQ, g_Q);
    cudaGetSymbolAddress((void**)&gK, g_K);
    cudaGetSymbolAddress((void**)&gV, g_V);
    cudaGetSymbolAddress((void**)&gH, g_heads);

    const int smem_gemm   = (128 * 128 + 64 * 129) * 4;                 //  98,560
    const int smem_scores = (256 * 129 + 4 * 256 * 9 + 4 * 128 + 440) * 4; // 172,768
    const int smem_av     = (256 * 129 + 16 * 32 * 34) * 4;             // 201,728

    cudaFuncSetAttribute(gemm128_kernel, cudaFuncAttributeMaxDynamicSharedMemorySize, smem_gemm);
    cudaFuncSetAttribute(scores_kernel,  cudaFuncAttributeMaxDynamicSharedMemorySize, smem_scores);
    cudaFuncSetAttribute(av_kernel,      cudaFuncAttributeMaxDynamicSharedMemorySize, smem_av);

    // projections
    gemm128_kernel<<<ROWS / 64, 256, smem_gemm>>>(q,  Wq, gQ, 0);
    gemm128_kernel<<<ROWS / 64, 256, smem_gemm>>>(hx, Wk, gK, 0);
    gemm128_kernel<<<ROWS / 64, 256, smem_gemm>>>(hx, Wv, gV, 0);

    // scores (+edge MLP +mask +softmax)
    scores_kernel<<<dim3(NN / 32, BB), 512, smem_scores>>>(edge, mask,
                                                           mw1, mb1, mw2, mb2, mw3, mb3);
    // attn @ V
    av_kernel<<<dim3(NN / 32, BB), 512, smem_av>>>();

    // output projection (Wo already (128,128) row-major under c = h*16+v)
    gemm128_kernel<<<ROWS / 64, 256, smem_gemm>>>(gH, Wo, (float*)d_out, 1);
}

// round 3
// speedup vs baseline: 1.2310x; 1.2310x over previous
#include <cuda_runtime.h>
#include <math.h>
#include <stdint.h>

// Problem constants
#define BB   128
#define NN   256
#define DIN  128
#define HH   8
#define DK   16
#define HK   128            // H*DK
#define ROWS (BB*NN)        // 32768
#define NORMC 0.25f         // 1/sqrt(16)
#define PAD  68             // smem row stride (floats) for K/V/Q tiles

// ---------------- device-global scratch ----------------
__device__ float g_Q[(size_t)ROWS * HK];      // [b*N+n][h*16+k]
__device__ float g_K[(size_t)ROWS * HK];
__device__ float g_V[(size_t)ROWS * HK];
__device__ float g_heads[(size_t)ROWS * HK];  // [b*N+q][h*16+v]

// PWL table for the edge MLP: f_h(e) = slope[seg][h]*e + inter[seg][h]
__device__ float g_breaks[512];               // ascending segment upper bounds (padded 3e38)
__device__ float g_tab[512 * 16];             // [seg][0..7 slope, 8..15 inter]

// =====================================================================
// PWL build: the edge MLP (scalar in) is exactly piecewise linear in e.
// Breakpoints: 16 layer-1 relu thresholds + per-interval layer-2 zero
// crossings (<=272). Per segment compute analytic slope/intercept for
// the 8 head outputs. One block, 512 threads.
// =====================================================================
__global__ void pwl_build_kernel(const float* __restrict__ mw1, const float* __restrict__ mb1,
                                 const float* __restrict__ mw2, const float* __restrict__ mb2,
                                 const float* __restrict__ mw3, const float* __restrict__ mb3)
{
    __shared__ float w1[16], b1[16], w2[256], b2[16], w3[128], b3[8];
    __shared__ float tsort[16];
    __shared__ float cand[512];
    __shared__ int   cnt;

    const int tid = threadIdx.x;
    if (tid < 16)  { w1[tid] = mw1[tid]; b1[tid] = mb1[tid]; b2[tid] = mb2[tid]; }
    if (tid < 256) w2[tid] = mw2[tid];
    if (tid < 128) w3[tid] = mw3[tid];
    if (tid < 8)   b3[tid] = mb3[tid];
    cand[tid] = 3.0e38f;
    if (tid == 0) cnt = 16;
    __syncthreads();

    // layer-1 thresholds
    if (tid < 16) {
        float t = (w1[tid] != 0.f) ? (-b1[tid] / w1[tid]) : 3.0e38f;
        cand[tid] = t;
    }
    __syncthreads();
    if (tid == 0) {
        for (int i = 0; i < 16; i++) tsort[i] = cand[i];
        for (int i = 1; i < 16; i++) {
            float v = tsort[i]; int k = i - 1;
            while (k >= 0 && tsort[k] > v) { tsort[k + 1] = tsort[k]; k--; }
            tsort[k + 1] = v;
        }
    }
    __syncthreads();

    // layer-2 zero crossings, per (interval, channel)
    if (tid < 17 * 16) {
        int iv = tid >> 4, c = tid & 15;
        float lo = (iv == 0)  ? -3.0e38f : tsort[iv - 1];
        float hi = (iv == 16) ?  3.0e38f : tsort[iv];
        if (lo < hi) {
            float m;
            if (lo <= -1e30f && hi >= 1e30f) m = 0.f;
            else if (lo <= -1e30f)           m = hi - 1.f;
            else if (hi >=  1e30f)           m = lo + 1.f;
            else                             m = 0.5f * (lo + hi);
            float g = 0.f, q = b2[c];
            for (int n = 0; n < 16; n++) {
                if (fmaf(m, w1[n], b1[n]) > 0.f) {
                    g = fmaf(w1[n], w2[n * 16 + c], g);
                    q = fmaf(b1[n], w2[n * 16 + c], q);
                }
            }
            if (g != 0.f) {
                float x = -q / g;
                if (x > lo && x < hi && fabsf(x) < 1e30f) {
                    int k = atomicAdd(&cnt, 1);
                    cand[k] = x;
                }
            }
        }
    }
    __syncthreads();
    const int ncand = cnt;   // <= 16 + 272 = 288

    // bitonic sort of 512 (pads = 3e38 go to the end)
    for (int k = 2; k <= 512; k <<= 1) {
        for (int j = k >> 1; j > 0; j >>= 1) {
            int ixj = tid ^ j;
            if (ixj > tid) {
                bool up = (tid & k) == 0;
                float a = cand[tid], b = cand[ixj];
                if ((a > b) == up) { cand[tid] = b; cand[ixj] = a; }
            }
            __syncthreads();
        }
    }

    g_breaks[tid] = (tid < ncand) ? cand[tid] : 3.0e38f;

    // per-segment analytic slope / intercept (no cancellation)
    if (tid <= ncand) {
        float lo = (tid == 0)     ? -3.0e38f : cand[tid - 1];
        float hi = (tid == ncand) ?  3.0e38f : cand[tid];
        float m;
        if (lo <= -1e30f && hi >= 1e30f) m = 0.f;
        else if (lo <= -1e30f)           m = hi - 1.f;
        else if (hi >=  1e30f)           m = lo + 1.f;
        else                             m = 0.5f * (lo + hi);

        float slope[8], inter[8];
        for (int h = 0; h < 8; h++) { slope[h] = 0.f; inter[h] = b3[h]; }
        for (int c = 0; c < 16; c++) {
            float gc = 0.f, qc = b2[c];
            for (int n = 0; n < 16; n++) {
                if (fmaf(m, w1[n], b1[n]) > 0.f) {
                    gc = fmaf(w1[n], w2[n * 16 + c], gc);
                    qc = fmaf(b1[n], w2[n * 16 + c], qc);
                }
            }
            if (fmaf(gc, m, qc) > 0.f) {
                for (int h = 0; h < 8; h++) {
                    slope[h] = fmaf(gc, w3[c * 8 + h], slope[h]);
                    inter[h] = fmaf(qc, w3[c * 8 + h], inter[h]);
                }
            }
        }
        for (int h = 0; h < 8; h++) {
            g_tab[tid * 16 + h]     = slope[h];
            g_tab[tid * 16 + 8 + h] = inter[h];
        }
    }
}

// =====================================================================
// Generic 128-wide GEMM (unchanged from R2)
// =====================================================================
__global__ void gemm128_kernel(const float* __restrict__ A,
                               const float* __restrict__ Wraw,
                               float* __restrict__ Out,
                               int mode)
{
    extern __shared__ float sm[];
    float* Wsm = sm;              // [128][128]
    float* Asm = sm + 128 * 128;  // [64][129]

    const int tid = threadIdx.x;
    const int row0 = blockIdx.x * 64;

    for (int idx = tid; idx < 128 * 128; idx += 256) {
        int d = idx >> 7, c = idx & 127;
        float w;
        if (mode == 0) w = Wraw[(c >> 4) * (DIN * 16) + d * 16 + (c & 15)];
        else           w = Wraw[d * 128 + c];
        Wsm[d * 128 + c] = w;
    }
    for (int idx = tid; idx < 64 * 128; idx += 256) {
        int r = idx >> 7, d = idx & 127;
        Asm[r * 129 + d] = A[(size_t)(row0 + r) * 128 + d];
    }
    __syncthreads();

    const int tx = tid & 15, ty = tid >> 4;
    const int c0 = tx * 8;
    const int r0 = ty * 4;
    float acc[4][8];
#pragma unroll
    for (int u = 0; u < 4; u++)
#pragma unroll
        for (int k = 0; k < 8; k++) acc[u][k] = 0.f;

#pragma unroll 4
    for (int d = 0; d < 128; d++) {
        float wv[8];
#pragma unroll
        for (int k = 0; k < 8; k++) wv[k] = Wsm[d * 128 + c0 + k];
#pragma unroll
        for (int u = 0; u < 4; u++) {
            float a = Asm[(r0 + u) * 129 + d];
#pragma unroll
            for (int k = 0; k < 8; k++) acc[u][k] = fmaf(a, wv[k], acc[u][k]);
        }
    }
#pragma unroll
    for (int u = 0; u < 4; u++)
#pragma unroll
        for (int k = 0; k < 8; k++)
            Out[(size_t)(row0 + r0 + u) * 128 + c0 + k] = acc[u][k];
}

// =====================================================================
// Fused attention: per block (b, 32-row i-tile, head-half of 4 heads).
// Stages K/V halves in smem, PWL edge-bias computed once per (i,j),
// QK^T + bias + mask + softmax + AV all fused; writes g_heads directly.
// grid (16, 128), 512 threads.
// smem floats: 2*256*68 + 8*256*5 + 8*68 + 512 + 304*16 = 50976 (~199KB)
// =====================================================================
__global__ void __launch_bounds__(512, 1)
attn_fused_kernel(const float* __restrict__ Ebm, const int* __restrict__ mask)
{
    extern __shared__ float sm[];
    float* Ksm   = sm;                      // [256][68]
    float* Vsm   = Ksm + 256 * PAD;         // [256][68]
    float* biasm = Vsm + 256 * PAD;         // [8][256][5]
    float* Qsm   = biasm + 8 * 256 * 5;     // [8][68]
    float* sB    = Qsm + 8 * PAD;           // [512] segment upper bounds
    float* sT    = sB + 512;                // [304][16] slope/inter

    const int tid   = threadIdx.x;
    const int b     = blockIdx.y;
    const int itile = (blockIdx.x & 7) * 32;
    const int hh    = blockIdx.x >> 3;      // head half: 0 or 1

    // stage K/V halves (4 heads = 64 cols)
    {
        const float* Kg = g_K + (size_t)b * NN * HK + hh * 64;
        const float* Vg = g_V + (size_t)b * NN * HK + hh * 64;
        for (int idx = tid; idx < 256 * 64; idx += 512) {
            int j = idx >> 6, c = idx & 63;
            Ksm[j * PAD + c] = Kg[(size_t)j * HK + c];
            Vsm[j * PAD + c] = Vg[(size_t)j * HK + c];
        }
    }
    sB[tid] = g_breaks[tid];
    for (int idx = tid; idx < 304 * 16; idx += 512) sT[idx] = g_tab[idx];
    __syncthreads();

    const int warp = tid >> 5, lane = tid & 31;
    const int hl = warp & 3;          // local head 0..3
    const int rp = warp >> 2;         // row pair 0..3
    const int h16 = hl * 16;

    for (int grp = 0; grp < 4; grp++) {
        const int i0 = itile + grp * 8;

        // stage Q: 8 rows x 64 cols (this head half)
        {
            int r = tid >> 6, c = tid & 63;
            Qsm[r * PAD + c] = g_Q[(size_t)(b * NN + i0 + r) * HK + hh * 64 + c];
        }

        // ---- bias phase: PWL eval once per (i,j); 2048 pairs, 4/thread
#pragma unroll
        for (int p = 0; p < 4; p++) {
            int pi = tid + p * 512;
            int r = pi >> 8, j = pi & 255;
            size_t gidx = (size_t)(b * NN + i0 + r) * NN + j;
            float e = Ebm[gidx];
            int   mk = mask[gidx];
            int seg = 0;
#pragma unroll
            for (int st = 256; st >= 1; st >>= 1) {
                int cnd = seg + st;
                if (e >= sB[cnd - 1]) seg = cnd;
            }
            float* brow = biasm + (r * 256 + j) * 5;
            const float* tp = sT + seg * 16 + hh * 4;
#pragma unroll
            for (int u = 0; u < 4; u++) {
                float bias = fmaf(tp[u], e, tp[8 + u]);
                brow[u] = mk ? -INFINITY : bias;
            }
        }
        __syncthreads();

        // ---- scores + softmax + AV: warp = (head hl, row pair rp)
        {
            const int rl = rp * 2;
            float Qa[16], Qb[16];
#pragma unroll
            for (int k = 0; k < 16; k++) {
                Qa[k] = Qsm[rl * PAD + h16 + k];
                Qb[k] = Qsm[(rl + 1) * PAD + h16 + k];
            }

            float sa[8], sb[8];
#pragma unroll
            for (int t = 0; t < 8; t++) {
                int j = lane + 32 * t;
                const float4* kp = (const float4*)(Ksm + j * PAD + h16);
                float da = 0.f, db = 0.f;
#pragma unroll
                for (int kq = 0; kq < 4; kq++) {
                    float4 kv = kp[kq];
                    da = fmaf(Qa[kq*4+0], kv.x, da); db = fmaf(Qb[kq*4+0], kv.x, db);
                    da = fmaf(Qa[kq*4+1], kv.y, da); db = fmaf(Qb[kq*4+1], kv.y, db);
                    da = fmaf(Qa[kq*4+2], kv.z, da); db = fmaf(Qb[kq*4+2], kv.z, db);
                    da = fmaf(Qa[kq*4+3], kv.w, da); db = fmaf(Qb[kq*4+3], kv.w, db);
                }
                float ba = biasm[(rl * 256 + j) * 5 + hl];
                float bb = biasm[((rl + 1) * 256 + j) * 5 + hl];
                sa[t] = (ba == -INFINITY) ? -INFINITY : fmaf(NORMC, da, ba);
                sb[t] = (bb == -INFINITY) ? -INFINITY : fmaf(NORMC, db, bb);
            }
            float ma = sa[0], mb_ = sb[0];
#pragma unroll
            for (int t = 1; t < 8; t++) { ma = fmaxf(ma, sa[t]); mb_ = fmaxf(mb_, sb[t]); }
#pragma unroll
            for (int o = 16; o > 0; o >>= 1) {
                ma  = fmaxf(ma,  __shfl_xor_sync(0xffffffffu, ma,  o));
                mb_ = fmaxf(mb_, __shfl_xor_sync(0xffffffffu, mb_, o));
            }
            float pa[8], pb[8];
            float suma = 0.f, sumb = 0.f;
#pragma unroll
            for (int t = 0; t < 8; t++) {
                pa[t] = __expf(sa[t] - ma);  suma += pa[t];
                pb[t] = __expf(sb[t] - mb_); sumb += pb[t];
            }
#pragma unroll
            for (int o = 16; o > 0; o >>= 1) {
                suma += __shfl_xor_sync(0xffffffffu, suma, o);
                sumb += __shfl_xor_sync(0xffffffffu, sumb, o);
            }
            float inva = 1.f / suma, invb = 1.f / sumb;

            // AV with unnormalized probs
            float acc[32];
#pragma unroll
            for (int i = 0; i < 32; i++) acc[i] = 0.f;
#pragma unroll
            for (int t = 0; t < 8; t++) {
                int j = lane + 32 * t;
                const float4* vp = (const float4*)(Vsm + j * PAD + h16);
#pragma unroll
                for (int kq = 0; kq < 4; kq++) {
                    float4 vv = vp[kq];
                    acc[kq*4+0]    = fmaf(pa[t], vv.x, acc[kq*4+0]);
                    acc[kq*4+1]    = fmaf(pa[t], vv.y, acc[kq*4+1]);
                    acc[kq*4+2]    = fmaf(pa[t], vv.z, acc[kq*4+2]);
                    acc[kq*4+3]    = fmaf(pa[t], vv.w, acc[kq*4+3]);
                    acc[16+kq*4+0] = fmaf(pb[t], vv.x, acc[16+kq*4+0]);
                    acc[16+kq*4+1] = fmaf(pb[t], vv.y, acc[16+kq*4+1]);
                    acc[16+kq*4+2] = fmaf(pb[t], vv.z, acc[16+kq*4+2]);
                    acc[16+kq*4+3] = fmaf(pb[t], vv.w, acc[16+kq*4+3]);
                }
            }
            // warp transpose-reduce: lane l ends with sum over lanes of acc[l]
#pragma unroll
            for (int d = 16; d >= 1; d >>= 1) {
                int sel = lane & d;
#pragma unroll
                for (int i = 0; i < d; i++) {
                    float send = sel ? acc[i] : acc[i + d];
                    float recv = __shfl_xor_sync(0xffffffffu, send, d);
                    acc[i] = (sel ? acc[i + d] : acc[i]) + recv;
                }
            }
            float inv = (lane < 16) ? inva : invb;
            int row = i0 + rl + (lane >> 4);
            g_heads[(size_t)(b * NN + row) * HK + (hh * 4 + hl) * 16 + (lane & 15)] = acc[0] * inv;
        }
        __syncthreads();
    }
}

// =====================================================================
// host launcher
// =====================================================================
extern "C" void kernel_launch(void* const* d_in, const int* in_sizes, int n_in,
                              void* d_out, int out_size)
{
    (void)in_sizes; (void)n_in; (void)out_size;
    const float* q    = (const float*)d_in[0];
    const float* hx   = (const float*)d_in[1];
    const int*   mask = (const int*)d_in[2];     // bool serialized as int32
    const float* edge = (const float*)d_in[3];
    const float* Wq   = (const float*)d_in[4];
    const float* Wk   = (const float*)d_in[5];
    const float* Wv   = (const float*)d_in[6];
    const float* Wo   = (const float*)d_in[7];
    const float* mw1  = (const float*)d_in[8];
    const float* mb1  = (const float*)d_in[9];
    const float* mw2  = (const float*)d_in[10];
    const float* mb2  = (const float*)d_in[11];
    const float* mw3  = (const float*)d_in[12];
    const float* mb3  = (const float*)d_in[13];

    float *gQ, *gK, *gV, *gH;
    cudaGetSymbolAddress((void**)&gQ, g_Q);
    cudaGetSymbolAddress((void**)&gK, g_K);
    cudaGetSymbolAddress((void**)&gV, g_V);
    cudaGetSymbolAddress((void**)&gH, g_heads);

    const int smem_gemm = (128 * 128 + 64 * 129) * 4;
    const int smem_attn = (2 * 256 * PAD + 8 * 256 * 5 + 8 * PAD + 512 + 304 * 16) * 4;

    cudaFuncSetAttribute(gemm128_kernel,    cudaFuncAttributeMaxDynamicSharedMemorySize, smem_gemm);
    cudaFuncSetAttribute(attn_fused_kernel, cudaFuncAttributeMaxDynamicSharedMemorySize, smem_attn);

    // PWL table for edge MLP (independent of gemms)
    pwl_build_kernel<<<1, 512>>>(mw1, mb1, mw2, mb2, mw3, mb3);

    // projections
    gemm128_kernel<<<ROWS / 64, 256, smem_gemm>>>(q,  Wq, gQ, 0);
    gemm128_kernel<<<ROWS / 64, 256, smem_gemm>>>(hx, Wk, gK, 0);
    gemm128_kernel<<<ROWS / 64, 256, smem_gemm>>>(hx, Wv, gV, 0);

    // fused scores + softmax + AV
    attn_fused_kernel<<<dim3(16, BB), 512, smem_attn>>>(edge, mask);

    // output projection
    gemm128_kernel<<<ROWS / 64, 256, smem_gemm>>>(gH, Wo, (float*)d_out, 1);
}

// round 4
// speedup vs baseline: 1.6849x; 1.3687x over previous
#include <cuda_runtime.h>
#include <math.h>
#include <stdint.h>

// Problem constants
#define BB   128
#define NN   256
#define DIN  128
#define HH   8
#define DK   16
#define HK   128            // H*DK
#define ROWS (BB*NN)        // 32768
#define NORMC 0.25f         // 1/sqrt(16)
#define PAD  68             // smem row stride (floats) for K/V/Q tiles
#define AS   132            // smem row stride for GEMM A tile

// ---------------- device-global scratch ----------------
__device__ float g_Q[(size_t)ROWS * HK];      // [b*N+n][h*16+k]
__device__ float g_K[(size_t)ROWS * HK];
__device__ float g_V[(size_t)ROWS * HK];
__device__ float g_heads[(size_t)ROWS * HK];  // [b*N+q][h*16+v]

// PWL table for the edge MLP: f_h(e) = slope*e + inter, interleaved pairs
__device__ float g_breaks[512];               // ascending segment upper bounds (pad 3e38)
__device__ float g_tab[512 * 16];             // [seg][h*2]=slope, [h*2+1]=inter
__device__ unsigned short g_seg[(size_t)BB * NN * NN]; // seg index | mask<<15

// =====================================================================
// PWL build (one block, 512 threads) — same math as R3, interleaved table
// =====================================================================
__global__ void pwl_build_kernel(const float* __restrict__ mw1, const float* __restrict__ mb1,
                                 const float* __restrict__ mw2, const float* __restrict__ mb2,
                                 const float* __restrict__ mw3, const float* __restrict__ mb3)
{
    __shared__ float w1[16], b1[16], w2[256], b2[16], w3[128], b3[8];
    __shared__ float tsort[16];
    __shared__ float cand[512];
    __shared__ int   cnt;

    const int tid = threadIdx.x;
    if (tid < 16)  { w1[tid] = mw1[tid]; b1[tid] = mb1[tid]; b2[tid] = mb2[tid]; }
    if (tid < 256) w2[tid] = mw2[tid];
    if (tid < 128) w3[tid] = mw3[tid];
    if (tid < 8)   b3[tid] = mb3[tid];
    cand[tid] = 3.0e38f;
    if (tid == 0) cnt = 16;
    __syncthreads();

    if (tid < 16) {
        float t = (w1[tid] != 0.f) ? (-b1[tid] / w1[tid]) : 3.0e38f;
        cand[tid] = t;
    }
    __syncthreads();
    if (tid == 0) {
        for (int i = 0; i < 16; i++) tsort[i] = cand[i];
        for (int i = 1; i < 16; i++) {
            float v = tsort[i]; int k = i - 1;
            while (k >= 0 && tsort[k] > v) { tsort[k + 1] = tsort[k]; k--; }
            tsort[k + 1] = v;
        }
    }
    __syncthreads();

    if (tid < 17 * 16) {
        int iv = tid >> 4, c = tid & 15;
        float lo = (iv == 0)  ? -3.0e38f : tsort[iv - 1];
        float hi = (iv == 16) ?  3.0e38f : tsort[iv];
        if (lo < hi) {
            float m;
            if (lo <= -1e30f && hi >= 1e30f) m = 0.f;
            else if (lo <= -1e30f)           m = hi - 1.f;
            else if (hi >=  1e30f)           m = lo + 1.f;
            else                             m = 0.5f * (lo + hi);
            float g = 0.f, q = b2[c];
            for (int n = 0; n < 16; n++) {
                if (fmaf(m, w1[n], b1[n]) > 0.f) {
                    g = fmaf(w1[n], w2[n * 16 + c], g);
                    q = fmaf(b1[n], w2[n * 16 + c], q);
                }
            }
            if (g != 0.f) {
                float x = -q / g;
                if (x > lo && x < hi && fabsf(x) < 1e30f) {
                    int k = atomicAdd(&cnt, 1);
                    cand[k] = x;
                }
            }
        }
    }
    __syncthreads();
    const int ncand = cnt;

    for (int k = 2; k <= 512; k <<= 1) {
        for (int j = k >> 1; j > 0; j >>= 1) {
            int ixj = tid ^ j;
            if (ixj > tid) {
                bool up = (tid & k) == 0;
                float a = cand[tid], b = cand[ixj];
                if ((a > b) == up) { cand[tid] = b; cand[ixj] = a; }
            }
            __syncthreads();
        }
    }

    g_breaks[tid] = (tid < ncand) ? cand[tid] : 3.0e38f;

    if (tid <= ncand) {
        float lo = (tid == 0)     ? -3.0e38f : cand[tid - 1];
        float hi = (tid == ncand) ?  3.0e38f : cand[tid];
        float m;
        if (lo <= -1e30f && hi >= 1e30f) m = 0.f;
        else if (lo <= -1e30f)           m = hi - 1.f;
        else if (hi >=  1e30f)           m = lo + 1.f;
        else                             m = 0.5f * (lo + hi);

        float slope[8], inter[8];
        for (int h = 0; h < 8; h++) { slope[h] = 0.f; inter[h] = b3[h]; }
        for (int c = 0; c < 16; c++) {
            float gc = 0.f, qc = b2[c];
            for (int n = 0; n < 16; n++) {
                if (fmaf(m, w1[n], b1[n]) > 0.f) {
                    gc = fmaf(w1[n], w2[n * 16 + c], gc);
                    qc = fmaf(b1[n], w2[n * 16 + c], qc);
                }
            }
            if (fmaf(gc, m, qc) > 0.f) {
                for (int h = 0; h < 8; h++) {
                    slope[h] = fmaf(gc, w3[c * 8 + h], slope[h]);
                    inter[h] = fmaf(qc, w3[c * 8 + h], inter[h]);
                }
            }
        }
        for (int h = 0; h < 8; h++) {
            g_tab[tid * 16 + h * 2]     = slope[h];
            g_tab[tid * 16 + h * 2 + 1] = inter[h];
        }
    }
}

// =====================================================================
// seg kernel: per (b,i,j) binary-search segment; fold mask into bit 15.
// grid 4096 x 512 threads, one float4/int4 per thread.
// =====================================================================
__global__ void __launch_bounds__(512) seg_kernel(const float* __restrict__ Ebm,
                                                  const int* __restrict__ mask)
{
    __shared__ float sB[512];
    const int tid = threadIdx.x;
    sB[tid] = g_breaks[tid];
    __syncthreads();

    const size_t v = (size_t)blockIdx.x * 512 + tid;   // vec4 index
    float4 e4 = ((const float4*)Ebm)[v];
    int4   m4 = ((const int4*)mask)[v];
    ushort4 out;
    const float ev[4] = {e4.x, e4.y, e4.z, e4.w};
    const int   mv[4] = {m4.x, m4.y, m4.z, m4.w};
    unsigned short ov[4];
#pragma unroll
    for (int p = 0; p < 4; p++) {
        float e = ev[p];
        int seg = 0;
#pragma unroll
        for (int st = 256; st >= 1; st >>= 1) {
            int cnd = seg + st;
            if (e >= sB[cnd - 1]) seg = cnd;
        }
        ov[p] = (unsigned short)(seg | (mv[p] ? 0x8000 : 0));
    }
    out.x = ov[0]; out.y = ov[1]; out.z = ov[2]; out.w = ov[3];
    ((ushort4*)g_seg)[v] = out;
}

// =====================================================================
// GEMM body: Out[row][c] = sum_d A[row][d] * W[d][c]; 64 rows/block,
// 256 threads, per-thread 4x8 (cols tx*4 and 64+tx*4), LDS.128 only.
// =====================================================================
__device__ __forceinline__ void gemm_body(const float* __restrict__ A,
                                          const float* __restrict__ Wraw,
                                          float* __restrict__ Out,
                                          int mode, int row0)
{
    extern __shared__ float sm[];
    float* Wsm = sm;              // [128][128]
    float* Asm = sm + 128 * 128;  // [64][AS]

    const int tid = threadIdx.x;

    for (int i4 = tid; i4 < 4096; i4 += 256) {
        int d = i4 >> 5, c4 = (i4 & 31) * 4;
        float4 w;
        if (mode == 0) w = *(const float4*)(Wraw + (c4 >> 4) * (DIN * 16) + d * 16 + (c4 & 15));
        else           w = *(const float4*)(Wraw + d * 128 + c4);
        *(float4*)(Wsm + d * 128 + c4) = w;
    }
    for (int i4 = tid; i4 < 2048; i4 += 256) {
        int r = i4 >> 5, c4 = (i4 & 31) * 4;
        *(float4*)(Asm + r * AS + c4) = *(const float4*)(A + (size_t)(row0 + r) * 128 + c4);
    }
    __syncthreads();

    const int tx = tid & 15, ty = tid >> 4;
    const int ca = tx * 4;          // cols ca..ca+3 and 64+ca..64+ca+3
    const int r0 = ty * 4;
    float acc[4][8];
#pragma unroll
    for (int u = 0; u < 4; u++)
#pragma unroll
        for (int k = 0; k < 8; k++) acc[u][k] = 0.f;

#pragma unroll 2
    for (int dc = 0; dc < 128; dc += 4) {
        float4 a4[4];
#pragma unroll
        for (int u = 0; u < 4; u++) a4[u] = *(const float4*)(Asm + (r0 + u) * AS + dc);
#pragma unroll
        for (int dd = 0; dd < 4; dd++) {
            float4 w0 = *(const float4*)(Wsm + (dc + dd) * 128 + ca);
            float4 w1 = *(const float4*)(Wsm + (dc + dd) * 128 + 64 + ca);
            float wv[8] = {w0.x, w0.y, w0.z, w0.w, w1.x, w1.y, w1.z, w1.w};
#pragma unroll
            for (int u = 0; u < 4; u++) {
                float a = (dd == 0) ? a4[u].x : (dd == 1) ? a4[u].y : (dd == 2) ? a4[u].z : a4[u].w;
#pragma unroll
                for (int k = 0; k < 8; k++) acc[u][k] = fmaf(a, wv[k], acc[u][k]);
            }
        }
    }
#pragma unroll
    for (int u = 0; u < 4; u++) {
        float4 o0 = {acc[u][0], acc[u][1], acc[u][2], acc[u][3]};
        float4 o1 = {acc[u][4], acc[u][5], acc[u][6], acc[u][7]};
        float* orow = Out + (size_t)(row0 + r0 + u) * 128;
        *(float4*)(orow + ca)      = o0;
        *(float4*)(orow + 64 + ca) = o1;
    }
}

__global__ void __launch_bounds__(256) gemm_qkv_kernel(const float* __restrict__ q,
                                                       const float* __restrict__ hx,
                                                       const float* __restrict__ Wq,
                                                       const float* __restrict__ Wk,
                                                       const float* __restrict__ Wv)
{
    const int z = blockIdx.y;
    const float* A = (z == 0) ? q : hx;
    const float* W = (z == 0) ? Wq : (z == 1) ? Wk : Wv;
    float* Out = (z == 0) ? g_Q : (z == 1) ? g_K : g_V;
    gemm_body(A, W, Out, 0, blockIdx.x * 64);
}

__global__ void __launch_bounds__(256) gemm_out_kernel(const float* __restrict__ Wo,
                                                       float* __restrict__ Out)
{
    gemm_body(g_heads, Wo, Out, 1, blockIdx.x * 64);
}

// =====================================================================
// Fused attention: per block (b, 32-row i-tile, head-half of 4 heads).
// PWL bias via precomputed seg (no search), QK^T + softmax + AV fused.
// grid (16, 128), 512 threads.
// =====================================================================
__global__ void __launch_bounds__(512, 1)
attn_fused_kernel(const float* __restrict__ Ebm)
{
    extern __shared__ float sm[];
    float* Ksm   = sm;                      // [256][68]
    float* Vsm   = Ksm + 256 * PAD;         // [256][68]
    float* biasm = Vsm + 256 * PAD;         // [8][256][5]
    float* Qsm   = biasm + 8 * 256 * 5;     // [8][68]
    float* sT    = Qsm + 8 * PAD;           // [304][16] interleaved slope/inter

    const int tid   = threadIdx.x;
    const int b     = blockIdx.y;
    const int itile = (blockIdx.x & 7) * 32;
    const int hh    = blockIdx.x >> 3;      // head half: 0 or 1

    // stage K/V halves (4 heads = 64 cols), float4
    {
        const float* Kg = g_K + (size_t)b * NN * HK + hh * 64;
        const float* Vg = g_V + (size_t)b * NN * HK + hh * 64;
        for (int i4 = tid; i4 < 256 * 16; i4 += 512) {
            int j = i4 >> 4, c4 = (i4 & 15) * 4;
            *(float4*)(Ksm + j * PAD + c4) = *(const float4*)(Kg + (size_t)j * HK + c4);
            *(float4*)(Vsm + j * PAD + c4) = *(const float4*)(Vg + (size_t)j * HK + c4);
        }
    }
    for (int idx = tid; idx < 304 * 16; idx += 512) sT[idx] = g_tab[idx];
    __syncthreads();

    const int warp = tid >> 5, lane = tid & 31;
    const int hl = warp & 3;          // local head 0..3
    const int rp = warp >> 2;         // row pair 0..3
    const int h16 = hl * 16;

    for (int grp = 0; grp < 4; grp++) {
        const int i0 = itile + grp * 8;

        // stage Q: 8 rows x 64 cols, float4 (128 threads)
        if (tid < 128) {
            int r = tid >> 4, c4 = (tid & 15) * 4;
            *(float4*)(Qsm + r * PAD + c4) =
                *(const float4*)(g_Q + (size_t)(b * NN + i0 + r) * HK + hh * 64 + c4);
        }

        // ---- bias phase: one float4 of (i,j) pairs per thread
        {
            const int r  = tid >> 6;          // 0..7
            const int j0 = (tid & 63) * 4;
            const size_t gi = (size_t)(b * NN + i0 + r) * NN + j0;
            float4 e4 = *(const float4*)(Ebm + gi);
            ushort4 s4 = *(const ushort4*)(g_seg + gi);
            const float ev[4] = {e4.x, e4.y, e4.z, e4.w};
            const unsigned short sv[4] = {s4.x, s4.y, s4.z, s4.w};
            float* brow = biasm + (r * 256 + j0) * 5;
#pragma unroll
            for (int p = 0; p < 4; p++) {
                int seg = sv[p] & 0x7fff;
                bool mk = (sv[p] & 0x8000) != 0;
                float e = ev[p];
                float4 t0 = *(const float4*)(sT + seg * 16 + hh * 8);
                float4 t1 = *(const float4*)(sT + seg * 16 + hh * 8 + 4);
                brow[p * 5 + 0] = mk ? -INFINITY : fmaf(t0.x, e, t0.y);
                brow[p * 5 + 1] = mk ? -INFINITY : fmaf(t0.z, e, t0.w);
                brow[p * 5 + 2] = mk ? -INFINITY : fmaf(t1.x, e, t1.y);
                brow[p * 5 + 3] = mk ? -INFINITY : fmaf(t1.z, e, t1.w);
            }
        }
        __syncthreads();

        // ---- scores + softmax + AV: warp = (head hl, row pair rp)
        {
            const int rl = rp * 2;
            float Qa[16], Qb[16];
#pragma unroll
            for (int k = 0; k < 16; k++) {
                Qa[k] = Qsm[rl * PAD + h16 + k];
                Qb[k] = Qsm[(rl + 1) * PAD + h16 + k];
            }

            float sa[8], sb[8];
#pragma unroll
            for (int t = 0; t < 8; t++) {
                int j = lane + 32 * t;
                const float4* kp = (const float4*)(Ksm + j * PAD + h16);
                float da = 0.f, db = 0.f;
#pragma unroll
                for (int kq = 0; kq < 4; kq++) {
                    float4 kv = kp[kq];
                    da = fmaf(Qa[kq*4+0], kv.x, da); db = fmaf(Qb[kq*4+0], kv.x, db);
                    da = fmaf(Qa[kq*4+1], kv.y, da); db = fmaf(Qb[kq*4+1], kv.y, db);
                    da = fmaf(Qa[kq*4+2], kv.z, da); db = fmaf(Qb[kq*4+2], kv.z, db);
                    da = fmaf(Qa[kq*4+3], kv.w, da); db = fmaf(Qb[kq*4+3], kv.w, db);
                }
                float ba = biasm[(rl * 256 + j) * 5 + hl];
                float bb = biasm[((rl + 1) * 256 + j) * 5 + hl];
                sa[t] = (ba == -INFINITY) ? -INFINITY : fmaf(NORMC, da, ba);
                sb[t] = (bb == -INFINITY) ? -INFINITY : fmaf(NORMC, db, bb);
            }
            float ma = sa[0], mb_ = sb[0];
#pragma unroll
            for (int t = 1; t < 8; t++) { ma = fmaxf(ma, sa[t]); mb_ = fmaxf(mb_, sb[t]); }
#pragma unroll
            for (int o = 16; o > 0; o >>= 1) {
                ma  = fmaxf(ma,  __shfl_xor_sync(0xffffffffu, ma,  o));
                mb_ = fmaxf(mb_, __shfl_xor_sync(0xffffffffu, mb_, o));
            }
            float pa[8], pb[8];
            float suma = 0.f, sumb = 0.f;
#pragma unroll
            for (int t = 0; t < 8; t++) {
                pa[t] = __expf(sa[t] - ma);  suma += pa[t];
                pb[t] = __expf(sb[t] - mb_); sumb += pb[t];
            }
#pragma unroll
            for (int o = 16; o > 0; o >>= 1) {
                suma += __shfl_xor_sync(0xffffffffu, suma, o);
                sumb += __shfl_xor_sync(0xffffffffu, sumb, o);
            }
            float inva = 1.f / suma, invb = 1.f / sumb;

            float acc[32];
#pragma unroll
            for (int i = 0; i < 32; i++) acc[i] = 0.f;
#pragma unroll
            for (int t = 0; t < 8; t++) {
                int j = lane + 32 * t;
                const float4* vp = (const float4*)(Vsm + j * PAD + h16);
#pragma unroll
                for (int kq = 0; kq < 4; kq++) {
                    float4 vv = vp[kq];
                    acc[kq*4+0]    = fmaf(pa[t], vv.x, acc[kq*4+0]);
                    acc[kq*4+1]    = fmaf(pa[t], vv.y, acc[kq*4+1]);
                    acc[kq*4+2]    = fmaf(pa[t], vv.z, acc[kq*4+2]);
                    acc[kq*4+3]    = fmaf(pa[t], vv.w, acc[kq*4+3]);
                    acc[16+kq*4+0] = fmaf(pb[t], vv.x, acc[16+kq*4+0]);
                    acc[16+kq*4+1] = fmaf(pb[t], vv.y, acc[16+kq*4+1]);
                    acc[16+kq*4+2] = fmaf(pb[t], vv.z, acc[16+kq*4+2]);
                    acc[16+kq*4+3] = fmaf(pb[t], vv.w, acc[16+kq*4+3]);
                }
            }
#pragma unroll
            for (int d = 16; d >= 1; d >>= 1) {
                int sel = lane & d;
#pragma unroll
                for (int i = 0; i < d; i++) {
                    float send = sel ? acc[i] : acc[i + d];
                    float recv = __shfl_xor_sync(0xffffffffu, send, d);
                    acc[i] = (sel ? acc[i + d] : acc[i]) + recv;
                }
            }
            float inv = (lane < 16) ? inva : invb;
            int row = i0 + rl + (lane >> 4);
            g_heads[(size_t)(b * NN + row) * HK + (hh * 4 + hl) * 16 + (lane & 15)] = acc[0] * inv;
        }
        __syncthreads();
    }
}

// =====================================================================
// host launcher
// =====================================================================
extern "C" void kernel_launch(void* const* d_in, const int* in_sizes, int n_in,
                              void* d_out, int out_size)
{
    (void)in_sizes; (void)n_in; (void)out_size;
    const float* q    = (const float*)d_in[0];
    const float* hx   = (const float*)d_in[1];
    const int*   mask = (const int*)d_in[2];     // bool serialized as int32
    const float* edge = (const float*)d_in[3];
    const float* Wq   = (const float*)d_in[4];
    const float* Wk   = (const float*)d_in[5];
    const float* Wv   = (const float*)d_in[6];
    const float* Wo   = (const float*)d_in[7];
    const float* mw1  = (const float*)d_in[8];
    const float* mb1  = (const float*)d_in[9];
    const float* mw2  = (const float*)d_in[10];
    const float* mb2  = (const float*)d_in[11];
    const float* mw3  = (const float*)d_in[12];
    const float* mb3  = (const float*)d_in[13];

    const int smem_gemm = (128 * 128 + 64 * AS) * 4;                       // 99,328
    const int smem_attn = (2 * 256 * PAD + 8 * 256 * 5 + 8 * PAD + 304 * 16) * 4; // 201,856

    cudaFuncSetAttribute(gemm_qkv_kernel,   cudaFuncAttributeMaxDynamicSharedMemorySize, smem_gemm);
    cudaFuncSetAttribute(gemm_out_kernel,   cudaFuncAttributeMaxDynamicSharedMemorySize, smem_gemm);
    cudaFuncSetAttribute(attn_fused_kernel, cudaFuncAttributeMaxDynamicSharedMemorySize, smem_attn);

    // PWL table for edge MLP, then segment precompute
    pwl_build_kernel<<<1, 512>>>(mw1, mb1, mw2, mb2, mw3, mb3);

    // QKV projections in one launch
    gemm_qkv_kernel<<<dim3(ROWS / 64, 3), 256, smem_gemm>>>(q, hx, Wq, Wk, Wv);

    // segment indices (+mask fold)
    seg_kernel<<<(BB * NN * NN) / (512 * 4), 512>>>(edge, mask);

    // fused scores + softmax + AV
    attn_fused_kernel<<<dim3(16, BB), 512, smem_attn>>>(edge);

    // output projection
    gemm_out_kernel<<<ROWS / 64, 256, smem_gemm>>>(Wo, (float*)d_out);
}